// round 1
// baseline (speedup 1.0000x reference)
#include <cuda_runtime.h>

#define MFERNS 8
#define KBITS 12
#define DOUT 32
#define NIMG 64
#define CCH 8
#define HIMG 128
#define WIMG 128
#define HP 120
#define WP 120
#define HOUT 114
#define WOUT 114
#define TROWS 4096   // 2^K

// Scratch: votes[n][y][d][x]  (64*120*32*120 floats = ~118 MB)
__device__ float g_votes[(size_t)NIMG * HP * DOUT * WP];

// ---------------------------------------------------------------------------
// Kernel 1: fused bit-word + confidence + table lookup -> votes
// grid (HP, NIMG), block 128 (x = tid, 120 active)
// ---------------------------------------------------------------------------
__global__ __launch_bounds__(128)
void votes_kernel(const float* __restrict__ x,
                  const float* __restrict__ thr,
                  const float* __restrict__ table,
                  const int* __restrict__ chan_idx,
                  const int* __restrict__ offsets)
{
    __shared__ float sth[MFERNS * KBITS];
    __shared__ int so1[MFERNS * KBITS];
    __shared__ int so2[MFERNS * KBITS];

    const int tid = threadIdx.x;
    if (tid < MFERNS * KBITS) {
        sth[tid] = thr[tid];
        int c1 = chan_idx[tid * 2 + 0];
        int c2 = chan_idx[tid * 2 + 1];
        int dy1 = offsets[tid * 4 + 0];
        int dx1 = offsets[tid * 4 + 1];
        int dy2 = offsets[tid * 4 + 2];
        int dx2 = offsets[tid * 4 + 3];
        so1[tid] = c1 * HIMG * WIMG + dy1 * WIMG + dx1;
        so2[tid] = c2 * HIMG * WIMG + dy2 * WIMG + dx2;
    }
    __syncthreads();

    const int y = blockIdx.x;
    const int n = blockIdx.y;
    const int px = tid;
    if (px >= WP) return;

    // base pointer: pixel value at (m,k) is xb[soff] where soff = c*H*W + dy*W + dx
    const float* xb = x + (size_t)n * CCH * HIMG * WIMG + (size_t)y * WIMG + px;

    float acc[DOUT];
#pragma unroll
    for (int d = 0; d < DOUT; d++) acc[d] = 0.f;

#pragma unroll 1
    for (int m = 0; m < MFERNS; m++) {
        unsigned word = 0;
        float denom = 1.f;
#pragma unroll
        for (int k = 0; k < KBITS; k++) {
            const int mk = m * KBITS + k;
            float diff = __ldg(xb + so1[mk]) - __ldg(xb + so2[mk]);
            float z = (diff - sth[mk]) * 10.0f;   // 1/TEMP
            if (z > 0.f) word |= (1u << k);
            // sigmoid(|z|) = 1/(1+e^{-|z|});  conf = 1 / prod(1+e^{-|z|})
            denom *= (1.0f + __expf(-fabsf(z)));
        }
        const float conf = __frcp_rn(denom);

        const float4* trow = reinterpret_cast<const float4*>(
            table + ((size_t)m * TROWS + word) * DOUT);
#pragma unroll
        for (int j = 0; j < DOUT / 4; j++) {
            float4 t = __ldg(trow + j);
            acc[4 * j + 0] = fmaf(conf, t.x, acc[4 * j + 0]);
            acc[4 * j + 1] = fmaf(conf, t.y, acc[4 * j + 1]);
            acc[4 * j + 2] = fmaf(conf, t.z, acc[4 * j + 2]);
            acc[4 * j + 3] = fmaf(conf, t.w, acc[4 * j + 3]);
        }
    }

    // votes[n][y][d][x]
    float* vb = g_votes + (((size_t)n * HP + y) * DOUT) * WP + px;
#pragma unroll
    for (int d = 0; d < DOUT; d++)
        vb[(size_t)d * WP] = acc[d];
}

// ---------------------------------------------------------------------------
// Kernel 2: separable 7x7 avg pool (stride 1), votes -> out[n][d][Y][X]
// grid (4 X-strips, 4 d-groups, NIMG), block 256
//   warp w handles d = blockIdx.y*8 + w, lanes handle X = blockIdx.x*32 + lane
// ---------------------------------------------------------------------------
__global__ __launch_bounds__(256)
void pool_kernel(float* __restrict__ out)
{
    const int lane = threadIdx.x & 31;
    const int w    = threadIdx.x >> 5;
    const int X = blockIdx.x * 32 + lane;
    const int d = blockIdx.y * 8 + w;
    const int n = blockIdx.z;
    if (X >= WOUT) return;

    const float inv49 = 1.0f / 49.0f;
    float h0 = 0.f, h1 = 0.f, h2 = 0.f, h3 = 0.f, h4 = 0.f, h5 = 0.f;

    float* ob = out + ((size_t)n * DOUT + d) * (size_t)HOUT * WOUT + X;

#pragma unroll 4
    for (int y = 0; y < HP; y++) {
        const float* row =
            g_votes + (((size_t)n * HP + y) * DOUT + d) * WP + X;
        float h = row[0] + row[1] + row[2] + row[3] + row[4] + row[5] + row[6];
        if (y >= 6) {
            float s = h + h0 + h1 + h2 + h3 + h4 + h5;
            ob[(size_t)(y - 6) * WOUT] = s * inv49;
        }
        h5 = h4; h4 = h3; h3 = h2; h2 = h1; h1 = h0; h0 = h;
    }
}

// ---------------------------------------------------------------------------
extern "C" void kernel_launch(void* const* d_in, const int* in_sizes, int n_in,
                              void* d_out, int out_size)
{
    const float* x        = (const float*)d_in[0];
    const float* thr      = (const float*)d_in[1];
    const float* table    = (const float*)d_in[2];
    const int*   chan_idx = (const int*)d_in[3];
    const int*   offsets  = (const int*)d_in[4];
    float* out = (float*)d_out;

    dim3 g1(HP, NIMG);
    votes_kernel<<<g1, 128>>>(x, thr, table, chan_idx, offsets);

    dim3 g2((WOUT + 31) / 32, DOUT / 8, NIMG);
    pool_kernel<<<g2, 256>>>(out);
}

// round 3
// speedup vs baseline: 1.4867x; 1.4867x over previous
#include <cuda_runtime.h>
#include <cuda_fp16.h>

#define MFERNS 8
#define KBITS 12
#define DOUT 32
#define NIMG 64
#define CCH 8
#define HIMG 128
#define WIMG 128
#define HP 120
#define WP 120
#define HOUT 114
#define WOUT 114
#define TROWS 4096

// fp16 voting table scratch: 8*4096*32 halves = 2 MB (stored as uint2 for 8B alignment)
__device__ uint2 g_table16[MFERNS * TROWS * DOUT / 4];

// votes scratch [n][d][y][x], float, padded; float4-aligned
__device__ float4 g_votes4[((size_t)NIMG * DOUT * HP * WP) / 4 + 8];

// ---------------------------------------------------------------------------
// Kernel 0: convert table fp32 -> fp16
// ---------------------------------------------------------------------------
__global__ __launch_bounds__(256)
void cvt_kernel(const float* __restrict__ table)
{
    int i = blockIdx.x * blockDim.x + threadIdx.x;   // 262144 float4 chunks
    float4 v = __ldg((const float4*)table + i);
    __half2 h0 = __floats2half2_rn(v.x, v.y);
    __half2 h1 = __floats2half2_rn(v.z, v.w);
    uint2 r;
    r.x = *(unsigned*)&h0;
    r.y = *(unsigned*)&h1;
    g_table16[i] = r;
}

// ---------------------------------------------------------------------------
// Kernel 1: bits + conf (phase A, thread=pixel) then cooperative table gather
// (phase B, lane = 4px x 8 d-chunks) -> votes[n][d][y][x]
// grid (HP, NIMG), block 128
// ---------------------------------------------------------------------------
__global__ __launch_bounds__(128)
void votes_kernel(const float* __restrict__ x,
                  const float* __restrict__ thr,
                  const int* __restrict__ chan_idx,
                  const int* __restrict__ offsets)
{
    // union region: phase A = x tile (8ch x 9rows x 128 = 36864 B)
    //               phase B = acc staging (120 x 33 floats = 15840 B)
    __shared__ float4 s_union4[9216 / 4];
    __shared__ int    s_word[HP * MFERNS];
    __shared__ float  s_conf[HP * MFERNS];
    __shared__ int    s_o1[96];
    __shared__ int    s_o2[96];
    __shared__ float  s_th[96];

    float* s_xf = (float*)s_union4;

    const int tid = threadIdx.x;
    const int y = blockIdx.x;
    const int n = blockIdx.y;

    if (tid < 96) {
        s_th[tid] = thr[tid];
        int c1 = chan_idx[2 * tid + 0];
        int c2 = chan_idx[2 * tid + 1];
        int dy1 = offsets[4 * tid + 0];
        int dx1 = offsets[4 * tid + 1];
        int dy2 = offsets[4 * tid + 2];
        int dx2 = offsets[4 * tid + 3];
        s_o1[tid] = c1 * 1152 + dy1 * 128 + dx1;
        s_o2[tid] = c2 * 1152 + dy2 * 128 + dx2;
    }

    // stage x tile: per channel rows y..y+8 are contiguous (9*128 floats)
    {
#pragma unroll
        for (int c = 0; c < CCH; c++) {
            const float4* src = (const float4*)x + ((size_t)((n * CCH + c) * HIMG + y)) * 32;
            float4* dst = s_union4 + c * 288;
            for (int j = tid; j < 288; j += 128)
                dst[j] = src[j];
        }
    }
    __syncthreads();

    // ---- Phase A: words + confidences ----
    const int px = tid;
    if (px < WP) {
#pragma unroll 2
        for (int m = 0; m < MFERNS; m++) {
            unsigned word = 0;
            float denom = 1.0f;
#pragma unroll
            for (int k = 0; k < KBITS; k++) {
                const int idx = m * KBITS + k;
                float diff = s_xf[s_o1[idx] + px] - s_xf[s_o2[idx] + px];
                float z = (diff - s_th[idx]) * 10.0f;     // 1/TEMP
                if (z > 0.0f) word |= (1u << k);
                denom *= (1.0f + __expf(-fabsf(z)));
            }
            s_word[px * MFERNS + m] = (int)word;
            s_conf[px * MFERNS + m] = __frcp_rn(denom);
        }
    }
    __syncthreads();

    // ---- Phase B: cooperative table gather ----
    float* s_acc = (float*)s_union4;          // [px][33] padded
    const int warp = tid >> 5;
    const int lane = tid & 31;
    const int dq = lane & 7;                  // d-chunk 0..7 (4 d each)
    const int pin = lane >> 3;                // pixel-in-group 0..3

    const __half* tab = (const __half*)g_table16;

#pragma unroll 1
    for (int pass = 0; pass < 8; pass++) {
        int px2 = pass * 16 + warp * 4 + pin;
        if (px2 < WP) {
            int   w_[MFERNS];
            float c_[MFERNS];
            uint2 r_[MFERNS];
#pragma unroll
            for (int m = 0; m < MFERNS; m++) {
                w_[m] = s_word[px2 * MFERNS + m];
                c_[m] = s_conf[px2 * MFERNS + m];
            }
#pragma unroll
            for (int m = 0; m < MFERNS; m++) {
                const uint2* p = (const uint2*)(tab +
                    ((size_t)(m * TROWS + w_[m]) * DOUT + dq * 4));
                r_[m] = __ldg(p);
            }
            float a0 = 0.f, a1 = 0.f, a2 = 0.f, a3 = 0.f;
#pragma unroll
            for (int m = 0; m < MFERNS; m++) {
                __half2 h0 = *(__half2*)&r_[m].x;
                __half2 h1 = *(__half2*)&r_[m].y;
                float2 f0 = __half22float2(h0);
                float2 f1 = __half22float2(h1);
                a0 = fmaf(c_[m], f0.x, a0);
                a1 = fmaf(c_[m], f0.y, a1);
                a2 = fmaf(c_[m], f1.x, a2);
                a3 = fmaf(c_[m], f1.y, a3);
            }
            int b = px2 * 33 + dq * 4;
            s_acc[b + 0] = a0;
            s_acc[b + 1] = a1;
            s_acc[b + 2] = a2;
            s_acc[b + 3] = a3;
        }
    }
    __syncthreads();

    // ---- coalesced store to votes[n][d][y][x] ----
    if (px < WP) {
        float* vb = (float*)g_votes4 + ((size_t)(n * DOUT) * HP + y) * WP + px;
#pragma unroll
        for (int d = 0; d < DOUT; d++)
            vb[(size_t)d * (HP * WP)] = s_acc[px * 33 + d];
    }
}

// ---------------------------------------------------------------------------
// Kernel 2: 7x7 avg pool, stride 1. votes[n][d][y][x] -> out[n][d][Y][X]
// warp = (nd plane, y-half). lane l<=28 produces X = 4l..4l+3.
// Register ring buffer (7 slots, statically indexed) for vertical window.
// grid 512, block 256 (8 warps)
// ---------------------------------------------------------------------------
__device__ __forceinline__ float4 hsum7(const float* r)
{
    float4 a = *(const float4*)r;
    float4 b = *(const float4*)(r + 4);
    float4 c = *(const float4*)(r + 8);
    float sb = b.x + b.y + b.z;          // b0+b1+b2
    float t = a.y + a.z + a.w;           // a1+a2+a3
    float4 h;
    h.x = a.x + t + sb;                  // cols 0..6
    h.y = t + sb + b.w;                  // cols 1..7
    h.z = a.z + a.w + sb + b.w + c.x;    // cols 2..8
    h.w = a.w + sb + b.w + c.x + c.y;    // cols 3..9
    return h;
}

__global__ __launch_bounds__(256)
void pool_kernel(float* __restrict__ out)
{
    const int warp = threadIdx.x >> 5;
    const int lane = threadIdx.x & 31;
    if (lane > 28) return;

    const int gw = blockIdx.x * 8 + warp;   // 0..4095
    const int h = gw & 1;
    const int nd = gw >> 1;                 // 0..2047 = n*32+d
    const int y0 = h * 57;

    const float* pv = (const float*)g_votes4 + (size_t)nd * (HP * WP) + (size_t)y0 * WP + 4 * lane;
    float* po = out + (size_t)nd * (HOUT * WOUT) + (size_t)y0 * WOUT + 4 * lane;

    const float inv49 = 1.0f / 49.0f;
    float4 ring[7];
    float4 vs = make_float4(0.f, 0.f, 0.f, 0.f);

    // prologue: rows 0..6
#pragma unroll
    for (int s = 0; s < 7; s++) {
        float4 hh = hsum7(pv + s * WP);
        ring[s] = hh;
        vs.x += hh.x; vs.y += hh.y; vs.z += hh.z; vs.w += hh.w;
    }
    {
        float2 o01 = make_float2(vs.x * inv49, vs.y * inv49);
        *(float2*)po = o01;
        if (lane < 28) {
            float2 o23 = make_float2(vs.z * inv49, vs.w * inv49);
            *(float2*)(po + 2) = o23;
        }
    }

    // rows 7..62, outputs Y = 1..56 (relative)
#pragma unroll 1
    for (int j = 1; j < 9; j++) {
#pragma unroll
        for (int s = 0; s < 7; s++) {
            int i = 7 * j + s;
            float4 hh = hsum7(pv + i * WP);
            vs.x += hh.x - ring[s].x;
            vs.y += hh.y - ring[s].y;
            vs.z += hh.z - ring[s].z;
            vs.w += hh.w - ring[s].w;
            ring[s] = hh;
            float* op = po + (size_t)(i - 6) * WOUT;
            float2 o01 = make_float2(vs.x * inv49, vs.y * inv49);
            *(float2*)op = o01;
            if (lane < 28) {
                float2 o23 = make_float2(vs.z * inv49, vs.w * inv49);
                *(float2*)(op + 2) = o23;
            }
        }
    }
}

// ---------------------------------------------------------------------------
extern "C" void kernel_launch(void* const* d_in, const int* in_sizes, int n_in,
                              void* d_out, int out_size)
{
    const float* x        = (const float*)d_in[0];
    const float* thr      = (const float*)d_in[1];
    const float* table    = (const float*)d_in[2];
    const int*   chan_idx = (const int*)d_in[3];
    const int*   offsets  = (const int*)d_in[4];
    float* out = (float*)d_out;

    cvt_kernel<<<1024, 256>>>(table);

    dim3 g1(HP, NIMG);
    votes_kernel<<<g1, 128>>>(x, thr, chan_idx, offsets);

    pool_kernel<<<512, 256>>>(out);
}

// round 4
// speedup vs baseline: 1.9035x; 1.2803x over previous
#include <cuda_runtime.h>
#include <cuda_fp16.h>

#define MFERNS 8
#define KBITS 12
#define DOUT 32
#define NIMG 64
#define CCH 8
#define HIMG 128
#define WIMG 128
#define HP 120
#define WP 120
#define HOUT 114
#define WOUT 114
#define TROWS 4096
#define Y4 4
#define BLK 512

// fp16 voting table scratch: 8*4096*32 halves = 2 MB
__device__ uint2 g_table16[MFERNS * TROWS * DOUT / 4];

// votes scratch [n][d][y][x], float; +8 float4 tail pad for pool edge reads
__device__ float4 g_votes4[((size_t)NIMG * DOUT * HP * WP) / 4 + 8];

// ---------------------------------------------------------------------------
// Kernel 0: convert table fp32 -> fp16
// ---------------------------------------------------------------------------
__global__ __launch_bounds__(256)
void cvt_kernel(const float* __restrict__ table)
{
    int i = blockIdx.x * blockDim.x + threadIdx.x;
    float4 v = __ldg((const float4*)table + i);
    __half2 h0 = __floats2half2_rn(v.x, v.y);
    __half2 h1 = __floats2half2_rn(v.z, v.w);
    uint2 r;
    r.x = *(unsigned*)&h0;
    r.y = *(unsigned*)&h1;
    g_table16[i] = r;
}

// ---------------------------------------------------------------------------
// Kernel 1: 4 rows per block, 512 threads.
//  Phase A (thread = (yl,px)): words + confidences into smem
//  Phase B (lane = 4px x 8 d-chunks): cooperative fp16 table gather, write
//           padded smem votes tile [4][32][121] (bank-conflict-free)
//  Phase C: coalesced bulk store to g_votes[n][d][y][x]
// Dynamic smem layout (floats):
//   [0,15488)      union: x tile (12288 used) -> votes tile (15488)
//   [15488,19328)  s_word (int, 3840)
//   [19328,23168)  s_conf (3840)
//   [23168,23264)  s_o1   [23264,23360) s_o2   [23360,23456) s_th
// total 23456 floats = 93824 B; __launch_bounds__(512,2) -> 2 blocks/SM
// ---------------------------------------------------------------------------
__global__ __launch_bounds__(BLK, 2)
void votes_kernel(const float* __restrict__ x,
                  const float* __restrict__ thr,
                  const int* __restrict__ chan_idx,
                  const int* __restrict__ offsets)
{
    extern __shared__ float sm[];
    float* s_un   = sm;
    int*   s_word = (int*)(sm + 15488);
    float* s_conf = sm + 19328;
    int*   s_o1   = (int*)(sm + 23168);
    int*   s_o2   = (int*)(sm + 23264);
    float* s_th   = sm + 23360;

    const int tid = threadIdx.x;
    const int y0  = blockIdx.x * Y4;
    const int n   = blockIdx.y;

    if (tid < 96) {
        s_th[tid] = thr[tid];
        int c1 = chan_idx[2 * tid + 0];
        int c2 = chan_idx[2 * tid + 1];
        int dy1 = offsets[4 * tid + 0];
        int dx1 = offsets[4 * tid + 1];
        int dy2 = offsets[4 * tid + 2];
        int dx2 = offsets[4 * tid + 3];
        s_o1[tid] = c1 * 1536 + dy1 * 128 + dx1;   // 1536 = 12 rows * 128
        s_o2[tid] = c2 * 1536 + dy2 * 128 + dx2;
    }

    // ---- stage x tile: 8 ch x 12 rows x 128 = 3072 float4 ----
    {
        const float4* xs = (const float4*)x;
        float4* st = (float4*)s_un;
        for (int i = tid; i < 3072; i += BLK) {
            int c = i / 384;              // 384 float4 per channel
            int r = i - c * 384;
            st[i] = __ldg(xs + (size_t)(n * CCH + c) * 4096 + y0 * 32 + r);
        }
    }
    __syncthreads();

    // ---- Phase A: words + confidences (480 active threads) ----
    {
        const int yl = tid >> 7;
        const int px = tid & 127;
        if (px < WP) {
            const int pbase = (yl * WP + px) * MFERNS;
            const int tb = yl * 128 + px;
#pragma unroll 2
            for (int m = 0; m < MFERNS; m++) {
                unsigned word = 0;
                float denom = 1.0f;
#pragma unroll
                for (int k = 0; k < KBITS; k++) {
                    const int idx = m * KBITS + k;
                    float diff = s_un[s_o1[idx] + tb] - s_un[s_o2[idx] + tb];
                    float z = (diff - s_th[idx]) * 10.0f;    // 1/TEMP
                    if (z > 0.0f) word |= (1u << k);
                    denom *= (1.0f + __expf(-fabsf(z)));
                }
                s_word[pbase + m] = (int)word;
                s_conf[pbase + m] = __frcp_rn(denom);
            }
        }
    }
    __syncthreads();

    // ---- Phase B: cooperative table gather -> smem votes tile ----
    const int warp = tid >> 5;
    const int lane = tid & 31;
    const int dq   = lane & 7;     // d-chunk (4 d each)
    const int pin  = lane >> 3;    // pixel-in-group

    const __half* tab = (const __half*)g_table16;

#pragma unroll 1
    for (int pass = 0; pass < 8; pass++) {
        int pglob = (pass * 16 + warp) * 4 + pin;     // 0..511
        if (pglob < Y4 * WP) {
            float c_[MFERNS];
            uint2 r_[MFERNS];
#pragma unroll
            for (int m = 0; m < MFERNS; m++) {
                int w = s_word[pglob * MFERNS + m];
                r_[m] = __ldg((const uint2*)(tab + ((size_t)(m * TROWS + w) * DOUT)) + dq);
                c_[m] = s_conf[pglob * MFERNS + m];
            }
            float a0 = 0.f, a1 = 0.f, a2 = 0.f, a3 = 0.f;
#pragma unroll
            for (int m = 0; m < MFERNS; m++) {
                float2 f0 = __half22float2(*(__half2*)&r_[m].x);
                float2 f1 = __half22float2(*(__half2*)&r_[m].y);
                a0 = fmaf(c_[m], f0.x, a0);
                a1 = fmaf(c_[m], f0.y, a1);
                a2 = fmaf(c_[m], f1.x, a2);
                a3 = fmaf(c_[m], f1.y, a3);
            }
            int yl2 = pglob / WP;
            int px2 = pglob - yl2 * WP;
            float* vp = s_un + (yl2 * DOUT + dq * 4) * 121 + px2;
            vp[0]   = a0;
            vp[121] = a1;
            vp[242] = a2;
            vp[363] = a3;
        }
    }
    __syncthreads();

    // ---- Phase C: coalesced store to g_votes[n][d][y][x] ----
    for (int r = warp; r < Y4 * DOUT; r += 16) {
        int yl2 = r >> 5;
        int d   = r & 31;
        const float* srcv = s_un + r * 121;
        float* dst = (float*)g_votes4 + ((size_t)(n * DOUT + d) * HP + y0 + yl2) * WP;
        for (int xx = lane; xx < WP; xx += 32)
            dst[xx] = srcv[xx];
    }
}

// ---------------------------------------------------------------------------
// Kernel 2: 7x7 avg pool, stride 1. votes[n][d][y][x] -> out[n][d][Y][X]
// ---------------------------------------------------------------------------
__device__ __forceinline__ float4 hsum7(const float* r)
{
    float4 a = *(const float4*)r;
    float4 b = *(const float4*)(r + 4);
    float4 c = *(const float4*)(r + 8);
    float sb = b.x + b.y + b.z;
    float t = a.y + a.z + a.w;
    float4 h;
    h.x = a.x + t + sb;
    h.y = t + sb + b.w;
    h.z = a.z + a.w + sb + b.w + c.x;
    h.w = a.w + sb + b.w + c.x + c.y;
    return h;
}

__global__ __launch_bounds__(256)
void pool_kernel(float* __restrict__ out)
{
    const int warp = threadIdx.x >> 5;
    const int lane = threadIdx.x & 31;
    if (lane > 28) return;

    const int gw = blockIdx.x * 8 + warp;
    const int h = gw & 1;
    const int nd = gw >> 1;
    const int y0 = h * 57;

    const float* pv = (const float*)g_votes4 + (size_t)nd * (HP * WP) + (size_t)y0 * WP + 4 * lane;
    float* po = out + (size_t)nd * (HOUT * WOUT) + (size_t)y0 * WOUT + 4 * lane;

    const float inv49 = 1.0f / 49.0f;
    float4 ring[7];
    float4 vs = make_float4(0.f, 0.f, 0.f, 0.f);

#pragma unroll
    for (int s = 0; s < 7; s++) {
        float4 hh = hsum7(pv + s * WP);
        ring[s] = hh;
        vs.x += hh.x; vs.y += hh.y; vs.z += hh.z; vs.w += hh.w;
    }
    {
        *(float2*)po = make_float2(vs.x * inv49, vs.y * inv49);
        if (lane < 28)
            *(float2*)(po + 2) = make_float2(vs.z * inv49, vs.w * inv49);
    }

#pragma unroll 1
    for (int j = 1; j < 9; j++) {
#pragma unroll
        for (int s = 0; s < 7; s++) {
            int i = 7 * j + s;
            float4 hh = hsum7(pv + i * WP);
            vs.x += hh.x - ring[s].x;
            vs.y += hh.y - ring[s].y;
            vs.z += hh.z - ring[s].z;
            vs.w += hh.w - ring[s].w;
            ring[s] = hh;
            float* op = po + (size_t)(i - 6) * WOUT;
            *(float2*)op = make_float2(vs.x * inv49, vs.y * inv49);
            if (lane < 28)
                *(float2*)(op + 2) = make_float2(vs.z * inv49, vs.w * inv49);
        }
    }
}

// ---------------------------------------------------------------------------
extern "C" void kernel_launch(void* const* d_in, const int* in_sizes, int n_in,
                              void* d_out, int out_size)
{
    const float* x        = (const float*)d_in[0];
    const float* thr      = (const float*)d_in[1];
    const float* table    = (const float*)d_in[2];
    const int*   chan_idx = (const int*)d_in[3];
    const int*   offsets  = (const int*)d_in[4];
    float* out = (float*)d_out;

    const int dyn_smem = 23456 * 4;   // 93824 B
    cudaFuncSetAttribute(votes_kernel,
                         cudaFuncAttributeMaxDynamicSharedMemorySize, dyn_smem);

    cvt_kernel<<<1024, 256>>>(table);

    dim3 g1(HP / Y4, NIMG);
    votes_kernel<<<g1, BLK, dyn_smem>>>(x, thr, chan_idx, offsets);

    pool_kernel<<<512, 256>>>(out);
}

// round 5
// speedup vs baseline: 2.0910x; 1.0985x over previous
#include <cuda_runtime.h>
#include <cuda_fp16.h>

#define MFERNS 8
#define KBITS 12
#define DOUT 32
#define NIMG 64
#define CCH 8
#define HIMG 128
#define WIMG 128
#define HP 120
#define WP 120
#define HOUT 114
#define WOUT 114
#define TROWS 4096
#define Y4 4
#define BLK 512
#define VS 122          // votes tile row stride (floats), even -> 8B-aligned float2 reads
#define HPAD 116        // h row length in halves (114 valid + 2 pad)

// fp16 voting table: 8*4096*32 halves = 2 MB
__device__ uint2 g_table16[MFERNS * TROWS * DOUT / 4];

// fp16 horizontal-sum scratch: h[n][d][y][116] halves, stored as uint2 (4 halves)
__device__ uint2 g_h2[(size_t)NIMG * DOUT * HP * (HPAD / 4)];

// ---------------------------------------------------------------------------
// Kernel 0: convert table fp32 -> fp16
// ---------------------------------------------------------------------------
__global__ __launch_bounds__(256)
void cvt_kernel(const float* __restrict__ table)
{
    int i = blockIdx.x * blockDim.x + threadIdx.x;
    float4 v = __ldg((const float4*)table + i);
    __half2 h0 = __floats2half2_rn(v.x, v.y);
    __half2 h1 = __floats2half2_rn(v.z, v.w);
    uint2 r;
    r.x = *(unsigned*)&h0;
    r.y = *(unsigned*)&h1;
    g_table16[i] = r;
}

// ---------------------------------------------------------------------------
// Kernel 1: 4 y-rows per block, 512 threads, 2 blocks/SM.
//  Phase A: words + confidences (thread = (yl,px))
//  Phase B: cooperative fp16 table gather (lane = 4px x 8 d-chunks) -> smem
//           votes tile [4*32][VS]
//  Phase H: horizontal 7-sum per row -> fp16 h[n][d][y][116] (global)
// ---------------------------------------------------------------------------
__global__ __launch_bounds__(BLK, 2)
void votes_kernel(const float* __restrict__ x,
                  const float* __restrict__ thr,
                  const int* __restrict__ chan_idx,
                  const int* __restrict__ offsets)
{
    extern __shared__ float s_un[];          // union: x tile (12288) / votes tile (128*VS)
    __shared__ int   s_word[Y4 * WP * MFERNS];
    __shared__ float s_conf[Y4 * WP * MFERNS];
    __shared__ int   s_o1[96];
    __shared__ int   s_o2[96];
    __shared__ float s_th[96];

    const int tid = threadIdx.x;
    const int y0  = blockIdx.x * Y4;
    const int n   = blockIdx.y;

    if (tid < 96) {
        s_th[tid] = thr[tid];
        int c1 = chan_idx[2 * tid + 0];
        int c2 = chan_idx[2 * tid + 1];
        int dy1 = offsets[4 * tid + 0];
        int dx1 = offsets[4 * tid + 1];
        int dy2 = offsets[4 * tid + 2];
        int dx2 = offsets[4 * tid + 3];
        s_o1[tid] = c1 * 1536 + dy1 * 128 + dx1;   // 1536 = 12 rows * 128
        s_o2[tid] = c2 * 1536 + dy2 * 128 + dx2;
    }

    // ---- stage x tile: 8 ch x 12 rows x 128 = 3072 float4 ----
    {
        const float4* xs = (const float4*)x;
        float4* st = (float4*)s_un;
        for (int i = tid; i < 3072; i += BLK) {
            int c = i / 384;
            int r = i - c * 384;
            st[i] = __ldg(xs + (size_t)(n * CCH + c) * 4096 + y0 * 32 + r);
        }
    }
    __syncthreads();

    // ---- Phase A: words + confidences (480 active threads) ----
    {
        const int yl = tid >> 7;
        const int px = tid & 127;
        if (px < WP) {
            const int pbase = (yl * WP + px) * MFERNS;
            const int tb = yl * 128 + px;
#pragma unroll 2
            for (int m = 0; m < MFERNS; m++) {
                unsigned word = 0;
                float denom = 1.0f;
#pragma unroll
                for (int k = 0; k < KBITS; k++) {
                    const int idx = m * KBITS + k;
                    float diff = s_un[s_o1[idx] + tb] - s_un[s_o2[idx] + tb];
                    float z = (diff - s_th[idx]) * 10.0f;    // 1/TEMP
                    if (z > 0.0f) word |= (1u << k);
                    denom *= (1.0f + __expf(-fabsf(z)));
                }
                s_word[pbase + m] = (int)word;
                s_conf[pbase + m] = __frcp_rn(denom);
            }
        }
    }
    __syncthreads();

    // ---- Phase B: cooperative table gather -> smem votes tile ----
    const int warp = tid >> 5;
    const int lane = tid & 31;
    const int dq   = lane & 7;
    const int pin  = lane >> 3;

    const __half* tab = (const __half*)g_table16;

#pragma unroll 1
    for (int pass = 0; pass < 8; pass++) {
        int g = pass * 16 + warp;                 // pixel group 0..127
        if (g < (Y4 * WP) / 4) {
            int pglob = g * 4 + pin;
            float c_[MFERNS];
            uint2 r_[MFERNS];
#pragma unroll
            for (int m = 0; m < MFERNS; m++) {
                int w = s_word[pglob * MFERNS + m];
                r_[m] = __ldg((const uint2*)(tab + ((size_t)(m * TROWS + w) * DOUT)) + dq);
                c_[m] = s_conf[pglob * MFERNS + m];
            }
            float a0 = 0.f, a1 = 0.f, a2 = 0.f, a3 = 0.f;
#pragma unroll
            for (int m = 0; m < MFERNS; m++) {
                float2 f0 = __half22float2(*(__half2*)&r_[m].x);
                float2 f1 = __half22float2(*(__half2*)&r_[m].y);
                a0 = fmaf(c_[m], f0.x, a0);
                a1 = fmaf(c_[m], f0.y, a1);
                a2 = fmaf(c_[m], f1.x, a2);
                a3 = fmaf(c_[m], f1.y, a3);
            }
            int yl2 = pglob / WP;
            int px2 = pglob - yl2 * WP;
            float* vp = s_un + (yl2 * DOUT + dq * 4) * VS + px2;
            vp[0]      = a0;
            vp[VS]     = a1;
            vp[2 * VS] = a2;
            vp[3 * VS] = a3;
        }
    }
    __syncthreads();

    // ---- Phase H: horizontal 7-sum -> fp16 h (lanes 0..28, warp strides rows) ----
    if (lane < 29) {
#pragma unroll 1
        for (int r = warp; r < Y4 * DOUT; r += 16) {
            int yl2 = r >> 5;
            int d   = r & 31;
            const float* row = s_un + r * VS + 4 * lane;
            // read 12 floats as 6 aligned float2
            float2 q0 = *(const float2*)(row + 0);
            float2 q1 = *(const float2*)(row + 2);
            float2 q2 = *(const float2*)(row + 4);
            float2 q3 = *(const float2*)(row + 6);
            float2 q4 = *(const float2*)(row + 8);
            float2 q5 = *(const float2*)(row + 10);
            float s36 = q1.y + q2.x + q2.y + q3.x;        // a3+a4+a5+a6
            float hx = q0.x + q0.y + q1.x + s36;          // a0..a6
            float hy = q0.y + q1.x + s36 + q3.y;          // a1..a7
            float hz = q1.x + s36 + q3.y + q4.x;          // a2..a8
            float hw = s36 + q3.y + q4.x + q4.y;          // a3..a9
            (void)q5;
            __half2 p0 = __floats2half2_rn(hx, hy);
            __half2 p1 = __floats2half2_rn(hz, hw);
            uint2 st;
            st.x = *(unsigned*)&p0;
            st.y = *(unsigned*)&p1;
            g_h2[((size_t)(n * DOUT + d) * HP + y0 + yl2) * (HPAD / 4) + lane] = st;
        }
    }
}

// ---------------------------------------------------------------------------
// Kernel 2: vertical 7-sum over fp16 h -> out[n][d][Y][X]
// warp = (nd plane, y-half); lane l<=28 handles X = 4l..4l+3.
// ---------------------------------------------------------------------------
__global__ __launch_bounds__(256)
void pool_kernel(float* __restrict__ out)
{
    const int warp = threadIdx.x >> 5;
    const int lane = threadIdx.x & 31;
    if (lane > 28) return;

    const int gw = blockIdx.x * 8 + warp;
    const int h = gw & 1;
    const int nd = gw >> 1;
    const int y0 = h * 57;

    const uint2* ph = g_h2 + ((size_t)nd * HP + y0) * (HPAD / 4) + lane;
    float* po = out + (size_t)nd * (HOUT * WOUT) + (size_t)y0 * WOUT + 4 * lane;

    const float inv49 = 1.0f / 49.0f;
    float4 ring[7];
    float4 vs = make_float4(0.f, 0.f, 0.f, 0.f);

#pragma unroll
    for (int s = 0; s < 7; s++) {
        uint2 v = __ldg(ph + s * (HPAD / 4));
        float2 f0 = __half22float2(*(__half2*)&v.x);
        float2 f1 = __half22float2(*(__half2*)&v.y);
        float4 hh = make_float4(f0.x, f0.y, f1.x, f1.y);
        ring[s] = hh;
        vs.x += hh.x; vs.y += hh.y; vs.z += hh.z; vs.w += hh.w;
    }
    {
        *(float2*)po = make_float2(vs.x * inv49, vs.y * inv49);
        if (lane < 28)
            *(float2*)(po + 2) = make_float2(vs.z * inv49, vs.w * inv49);
    }

#pragma unroll 1
    for (int j = 1; j < 9; j++) {
#pragma unroll
        for (int s = 0; s < 7; s++) {
            int i = 7 * j + s;
            uint2 v = __ldg(ph + i * (HPAD / 4));
            float2 f0 = __half22float2(*(__half2*)&v.x);
            float2 f1 = __half22float2(*(__half2*)&v.y);
            float4 hh = make_float4(f0.x, f0.y, f1.x, f1.y);
            vs.x += hh.x - ring[s].x;
            vs.y += hh.y - ring[s].y;
            vs.z += hh.z - ring[s].z;
            vs.w += hh.w - ring[s].w;
            ring[s] = hh;
            float* op = po + (size_t)(i - 6) * WOUT;
            *(float2*)op = make_float2(vs.x * inv49, vs.y * inv49);
            if (lane < 28)
                *(float2*)(op + 2) = make_float2(vs.z * inv49, vs.w * inv49);
        }
    }
}

// ---------------------------------------------------------------------------
extern "C" void kernel_launch(void* const* d_in, const int* in_sizes, int n_in,
                              void* d_out, int out_size)
{
    const float* x        = (const float*)d_in[0];
    const float* thr      = (const float*)d_in[1];
    const float* table    = (const float*)d_in[2];
    const int*   chan_idx = (const int*)d_in[3];
    const int*   offsets  = (const int*)d_in[4];
    float* out = (float*)d_out;

    // union tile: 128 rows * VS floats (+16 pad for lane-28 tail reads)
    const int dyn_smem = (Y4 * DOUT * VS + 16) * 4;
    cudaFuncSetAttribute(votes_kernel,
                         cudaFuncAttributeMaxDynamicSharedMemorySize, dyn_smem);

    cvt_kernel<<<1024, 256>>>(table);

    dim3 g1(HP / Y4, NIMG);
    votes_kernel<<<g1, BLK, dyn_smem>>>(x, thr, chan_idx, offsets);

    pool_kernel<<<512, 256>>>(out);
}